// round 3
// baseline (speedup 1.0000x reference)
#include <cuda_runtime.h>
#include <cuda_bf16.h>
#include <cstdint>
#include <math.h>

#define PX       48
#define PTOT     110592            // 48^3
#define NDIR     32
#define NRES     64
#define PCHUNK   256
#define NBLOCKS  (PTOT / PCHUNK)   // 432
#define NE       (4 * NDIR * NRES) // (b*2+c) -> 8192 floats

// ---------------- device scratch (static; no allocations) -------------------
__device__ float         g_dirs[3 * NDIR];   // prescaled by 8*log2(e)
__device__ float         g_K[NRES];          // exp(-8*lin_r)
__device__ float         g_E[NE];            // [(b*2+c)][d][r]
__device__ unsigned int  g_done;
__device__ ulonglong2    g_dwA[PTOT];        // (dup(b0c0), dup(b1c0))
__device__ ulonglong2    g_dwB[PTOT];        // (dup(b0c1), dup(b1c1))

// ---------------- asm helpers ------------------------------------------------
__device__ __forceinline__ unsigned long long pack2(float lo, float hi) {
    unsigned long long r;
    asm("mov.b64 %0, {%1, %2};" : "=l"(r) : "f"(lo), "f"(hi));
    return r;
}
__device__ __forceinline__ void unpack2(unsigned long long v, float& lo, float& hi) {
    asm("mov.b64 {%0, %1}, %2;" : "=f"(lo), "=f"(hi) : "l"(v));
}
__device__ __forceinline__ void fma2(unsigned long long& acc, unsigned long long ab,
                                     unsigned long long c) {
    asm("fma.rn.f32x2 %0, %1, %2, %0;" : "+l"(acc) : "l"(ab), "l"(c));
}
__device__ __forceinline__ float rcp_approx(float x) {
    float r;
    asm("rcp.approx.f32 %0, %1;" : "=f"(r) : "f"(x));
    return r;
}
__device__ __forceinline__ float ex2_approx(float x) {
    float r;
    asm("ex2.approx.f32 %0, %1;" : "=f"(r) : "f"(x));
    return r;
}

// ---------------- threefry2x32 (JAX partitionable path) ---------------------
__device__ __forceinline__ uint32_t rotl32(uint32_t x, int d) {
    return (x << d) | (x >> (32 - d));
}
__device__ void threefry2x32(uint32_t k0, uint32_t k1, uint32_t& x0, uint32_t& x1) {
    uint32_t k2 = k0 ^ k1 ^ 0x1BD11BDAu;
    x0 += k0; x1 += k1;
#define TFR(r) { x0 += x1; x1 = rotl32(x1, r); x1 ^= x0; }
    TFR(13) TFR(15) TFR(26) TFR(6)
    x0 += k1; x1 += k2 + 1u;
    TFR(17) TFR(29) TFR(16) TFR(24)
    x0 += k2; x1 += k0 + 2u;
    TFR(13) TFR(15) TFR(26) TFR(6)
    x0 += k0; x1 += k1 + 3u;
    TFR(17) TFR(29) TFR(16) TFR(24)
    x0 += k1; x1 += k2 + 4u;
    TFR(13) TFR(15) TFR(26) TFR(6)
    x0 += k2; x1 += k0 + 5u;
#undef TFR
}

__device__ float erfinv_f32(float x) {
    float w = -log1pf(-x * x);
    float p;
    if (w < 5.0f) {
        w = w - 2.5f;
        p =            2.81022636e-08f;
        p = fmaf(p, w, 3.43273939e-07f);
        p = fmaf(p, w, -3.5233877e-06f);
        p = fmaf(p, w, -4.39150654e-06f);
        p = fmaf(p, w, 0.00021858087f);
        p = fmaf(p, w, -0.00125372503f);
        p = fmaf(p, w, -0.00417768164f);
        p = fmaf(p, w, 0.246640727f);
        p = fmaf(p, w, 1.50140941f);
    } else {
        w = sqrtf(w) - 3.0f;
        p =            -0.000200214257f;
        p = fmaf(p, w, 0.000100950558f);
        p = fmaf(p, w, 0.00134934322f);
        p = fmaf(p, w, -0.00367342844f);
        p = fmaf(p, w, 0.00573950773f);
        p = fmaf(p, w, -0.0076224613f);
        p = fmaf(p, w, 0.00943887047f);
        p = fmaf(p, w, 1.00167406f);
        p = fmaf(p, w, 2.83297682f);
    }
    return p * x;
}

// ---------------- kernel A: init (block 0) + prep (all blocks) --------------
__global__ __launch_bounds__(256) void kernelA(const float* __restrict__ pred,
                                               const void* __restrict__ tgt) {
    int tid = threadIdx.x;
    int p = blockIdx.x * 256 + tid;

    // -- per-block dtype sniff (int64 targets: all odd 32-bit words are 0) --
    __shared__ int s_t64;
    if (tid == 0) {
        const int* ti = (const int*)tgt;
        int all0 = 1;
        for (int q = 0; q < 64; q++)
            if (ti[2 * q + 1] != 0) { all0 = 0; break; }
        s_t64 = all0;
    }

    // -- block 0: global init work --
    if (blockIdx.x == 0) {
        for (int i = tid; i < NE; i += 256) g_E[i] = 0.0f;
        if (tid == 0) g_done = 0u;

        __shared__ float sv[96];
        if (tid < 96) {
            uint32_t x0 = 0u, x1 = (uint32_t)tid;
            threefry2x32(0u, 17u, x0, x1);
            uint32_t bits = x0 ^ x1;
            float f = __uint_as_float((bits >> 9) | 0x3f800000u) - 1.0f;
            const float lo = -0.99999994f;
            float u = __fadd_rn(__fmul_rn(f, 2.0f), lo);
            u = fmaxf(u, lo);
            sv[tid] = 1.41421356237f * erfinv_f32(u);
        }
        __syncthreads();
        if (tid < NDIR) {
            float a = sv[tid], b = sv[NDIR + tid], c = sv[2 * NDIR + tid];
            float n = sqrtf(a * a + b * b + c * c);
            n = fmaxf(n, 1e-12f);
            const float PRE = 8.0f * 1.4426950408889634f;  // 8*log2(e)
            g_dirs[tid]            = (a / n) * PRE;
            g_dirs[NDIR + tid]     = (b / n) * PRE;
            g_dirs[2 * NDIR + tid] = (c / n) * PRE;
        }
        if (tid < NRES) {
            double radius = 1.1 * sqrt(3.0);
            double lin = -radius + (double)tid * (2.0 * radius / 63.0);
            g_K[tid] = (float)exp(-8.0 * lin);
        }
    } else {
        __syncthreads();  // match block-0 barrier count
    }
    __syncthreads();
    int t64 = s_t64;

    // -- prep: dw = softmax(pred) - onehot(tgt), channels 0 and 1, duplicated --
    float dw[2][2];
#pragma unroll
    for (int b = 0; b < 2; b++) {
        float x0 = pred[(b * 3 + 0) * PTOT + p];
        float x1 = pred[(b * 3 + 1) * PTOT + p];
        float x2 = pred[(b * 3 + 2) * PTOT + p];
        float m = fmaxf(x0, fmaxf(x1, x2));
        float e0 = expf(x0 - m), e1 = expf(x1 - m), e2 = expf(x2 - m);
        float s = e0 + e1 + e2;
        int tv;
        if (t64) tv = (int)((const long long*)tgt)[b * PTOT + p];
        else     tv = ((const int*)tgt)[b * PTOT + p];
        dw[b][0] = e0 / s - (tv == 0 ? 1.0f : 0.0f);
        dw[b][1] = e1 / s - (tv == 1 ? 1.0f : 0.0f);
    }
    ulonglong2 A, B;
    A.x = pack2(dw[0][0], dw[0][0]);   // dup(b0,c0)
    A.y = pack2(dw[1][0], dw[1][0]);   // dup(b1,c0)
    B.x = pack2(dw[0][1], dw[0][1]);   // dup(b0,c1)
    B.y = pack2(dw[1][1], dw[1][1]);   // dup(b1,c1)
    g_dwA[p] = A;
    g_dwB[p] = B;
}

// ---------------- kernel B: main accumulation + fused final -----------------
// block = 256-p chunk; warp w owns r in [w*8, w*8+8) as 4 r-pairs; lane = dir
__global__ __launch_bounds__(256, 3) void kernelB(float* __restrict__ out) {
    __shared__ ulonglong2 s_dwA[PCHUNK];
    __shared__ ulonglong2 s_dwB[PCHUNK];
    __shared__ float4     s_c[PCHUNK];
    __shared__ unsigned   s_ticket;

    int tid = threadIdx.x;
    int lane = tid & 31;
    int w = tid >> 5;
    int pbase = blockIdx.x * PCHUNK;

    // load phase: dw packs + voxel coords (one p per thread)
    {
        int p = pbase + tid;
        s_dwA[tid] = g_dwA[p];
        s_dwB[tid] = g_dwB[p];
        int ix = p / 2304;
        int rem = p - ix * 2304;
        int iy = rem / 48;
        int iz = rem - iy * 48;
        const float CSTEP = 2.0f / 47.0f;
        float4 c;
        c.x = fmaf((float)ix, CSTEP, -1.0f);
        c.y = fmaf((float)iy, CSTEP, -1.0f);
        c.z = fmaf((float)iz, CSTEP, -1.0f);
        c.w = 0.0f;
        s_c[tid] = c;
    }
    __syncthreads();

    float d0 = g_dirs[lane];           // prescaled by 8*log2(e)
    float d1 = g_dirs[NDIR + lane];
    float d2 = g_dirs[2 * NDIR + lane];

    float K[8];
#pragma unroll
    for (int k = 0; k < 8; k++) K[k] = g_K[w * 8 + k];

    // acc[bc][kp]: bc in {b0c0, b1c0, b0c1, b1c1}, kp packs (r=2kp, r=2kp+1)
    unsigned long long a00[4], a10[4], a01[4], a11[4];
#pragma unroll
    for (int kp = 0; kp < 4; kp++) { a00[kp] = a10[kp] = a01[kp] = a11[kp] = 0ull; }

    for (int i = 0; i < PCHUNK; i++) {
        float4 c = s_c[i];
        float nh = c.x * d0;
        nh = fmaf(c.y, d1, nh);
        nh = fmaf(c.z, d2, nh);
        float eb = ex2_approx(nh);           // exp(8*nh)

        ulonglong2 dA = s_dwA[i];
        ulonglong2 dB = s_dwB[i];
#pragma unroll
        for (int kp = 0; kp < 4; kp++) {
            float t0 = fmaf(eb, K[2 * kp + 0], 1.0f);
            float t1 = fmaf(eb, K[2 * kp + 1], 1.0f);
            float s0 = rcp_approx(t0);       // sigmoid(8*(lin_r - nh))
            float s1 = rcp_approx(t1);
            unsigned long long s01 = pack2(s0, s1);
            fma2(a00[kp], dA.x, s01);
            fma2(a10[kp], dA.y, s01);
            fma2(a01[kp], dB.x, s01);
            fma2(a11[kp], dB.y, s01);
        }
    }

    // flush: g_E[(b*2+c)][d][r]
#pragma unroll
    for (int kp = 0; kp < 4; kp++) {
        int r0 = w * 8 + 2 * kp;
        float v0, v1;
        unpack2(a00[kp], v0, v1);
        atomicAdd(&g_E[(0 * NDIR + lane) * NRES + r0],     v0);
        atomicAdd(&g_E[(0 * NDIR + lane) * NRES + r0 + 1], v1);
        unpack2(a01[kp], v0, v1);
        atomicAdd(&g_E[(1 * NDIR + lane) * NRES + r0],     v0);
        atomicAdd(&g_E[(1 * NDIR + lane) * NRES + r0 + 1], v1);
        unpack2(a10[kp], v0, v1);
        atomicAdd(&g_E[(2 * NDIR + lane) * NRES + r0],     v0);
        atomicAdd(&g_E[(2 * NDIR + lane) * NRES + r0 + 1], v1);
        unpack2(a11[kp], v0, v1);
        atomicAdd(&g_E[(3 * NDIR + lane) * NRES + r0],     v0);
        atomicAdd(&g_E[(3 * NDIR + lane) * NRES + r0 + 1], v1);
    }

    // last block computes the final loss
    __threadfence();
    __syncthreads();
    if (tid == 0) s_ticket = atomicAdd(&g_done, 1u);
    __syncthreads();
    if (s_ticket != (unsigned)(NBLOCKS - 1)) return;

    float sum = 0.0f;
    for (int idx = tid; idx < 4096; idx += 256) {
        int b = idx >> 11;
        int dr = idx & 2047;
        float e0 = g_E[(b * 2 + 0) * 2048 + dr];
        float e1 = g_E[(b * 2 + 1) * 2048 + dr];
        float e2 = -(e0 + e1);                 // channel-2 by cancellation
        sum += e0 * e0 + e1 * e1 + e2 * e2;
    }
    __shared__ float red[8];
#pragma unroll
    for (int off = 16; off > 0; off >>= 1)
        sum += __shfl_down_sync(0xFFFFFFFFu, sum, off);
    if ((tid & 31) == 0) red[tid >> 5] = sum;
    __syncthreads();
    if (tid < 8) {
        float v = red[tid];
#pragma unroll
        for (int off = 4; off > 0; off >>= 1)
            v += __shfl_down_sync(0xFFu, v, off);
        if (tid == 0) out[0] = v / 12288.0f;
    }
}

// ---------------- launcher ---------------------------------------------------
extern "C" void kernel_launch(void* const* d_in, const int* in_sizes, int n_in,
                              void* d_out, int out_size) {
    const float* pred = (const float*)d_in[0];
    const void*  tgt  = d_in[1];
    float* out = (float*)d_out;
    (void)in_sizes; (void)n_in; (void)out_size;

    kernelA<<<NBLOCKS, 256>>>(pred, tgt);
    kernelB<<<NBLOCKS, 256>>>(out);
}